// round 15
// baseline (speedup 1.0000x reference)
#include <cuda_runtime.h>
#include <cuda_bf16.h>
#include <math.h>
#include <stdint.h>
#include <cstdint>

#define Bm 512
#define Sm 64
#define Dm 128
#define EPSm 1e-5f
typedef unsigned long long ull;
typedef __nv_bfloat16 bf16;

// ---------------- scratch ----------------
__device__ float g_h[Bm*Sm*Dm];
__device__ float g_gx[(size_t)Sm*Bm*512];
__device__ __align__(16) bf16 g_vh[Bm*Sm*Dm], g_vl[Bm*Sm*Dm];
__device__ __align__(16) bf16 g_wgh[2*512*32],  g_wgl[2*512*32];   // [blk][o][h]
__device__ __align__(16) bf16 g_wuh[2*256*128], g_wul[2*256*128];
__device__ __align__(16) bf16 g_wdh[2*128*128], g_wdl[2*128*128];

// ---------------- f32x2 helpers ----------------
__device__ __forceinline__ ull pk2(float a, float b){ ull r; asm("mov.b64 %0, {%1,%2};" : "=l"(r) : "f"(a), "f"(b)); return r; }
__device__ __forceinline__ void upk2(ull v, float &a, float &b){ asm("mov.b64 {%0,%1}, %2;" : "=f"(a), "=f"(b) : "l"(v)); }
__device__ __forceinline__ ull fma2_(ull a, ull b, ull c){ ull d; asm("fma.rn.f32x2 %0, %1, %2, %3;" : "=l"(d) : "l"(a), "l"(b), "l"(c)); return d; }
__device__ __forceinline__ ull add2_(ull a, ull b){ ull d; asm("add.rn.f32x2 %0, %1, %2;" : "=l"(d) : "l"(a), "l"(b)); return d; }

// ---------------- mma helpers ----------------
__device__ __forceinline__ uint32_t s2u(const void* p){ return (uint32_t)__cvta_generic_to_shared(p); }
__device__ __forceinline__ void mma_bf16(float* c, const uint32_t* a, const uint32_t* b){
    asm("mma.sync.aligned.m16n8k16.row.col.f32.bf16.bf16.f32 "
        "{%0,%1,%2,%3}, {%4,%5,%6,%7}, {%8,%9}, {%0,%1,%2,%3};"
        : "+f"(c[0]), "+f"(c[1]), "+f"(c[2]), "+f"(c[3])
        : "r"(a[0]), "r"(a[1]), "r"(a[2]), "r"(a[3]), "r"(b[0]), "r"(b[1]));
}
__device__ __forceinline__ void ldsm4(uint32_t* r, uint32_t addr){
    asm volatile("ldmatrix.sync.aligned.m8n8.x4.shared.b16 {%0,%1,%2,%3}, [%4];"
        : "=r"(r[0]),"=r"(r[1]),"=r"(r[2]),"=r"(r[3]) : "r"(addr));
}
__device__ __forceinline__ void ldsm2(uint32_t* r, uint32_t addr){
    asm volatile("ldmatrix.sync.aligned.m8n8.x2.shared.b16 {%0,%1}, [%2];"
        : "=r"(r[0]),"=r"(r[1]) : "r"(addr));
}
__device__ __forceinline__ void mma3(float* c, const uint32_t* ah, const uint32_t* al,
                                     const uint32_t* bh, const uint32_t* bl){
    mma_bf16(c, ah, bh);
    mma_bf16(c, ah, bl);
    mma_bf16(c, al, bh);
}
__device__ __forceinline__ void bsplit(float x, bf16& h, bf16& l){
    h = __float2bfloat16(x);
    l = __float2bfloat16(x - __bfloat162float(h));
}
__device__ __forceinline__ float gelu_(float g){
    return 0.5f*g*(1.f + erff(g*0.70710678118f));
}

// LN one token -> split bf16 into padded smem row (stride 136)
__device__ __forceinline__ void ln_core(float4 v, float4 lw, int lane, bf16* Ah, bf16* Al, int tok){
    float s = v.x+v.y+v.z+v.w;
    float q = v.x*v.x+v.y*v.y+v.z*v.z+v.w*v.w;
    #pragma unroll
    for (int o=16;o>0;o>>=1){ s += __shfl_xor_sync(0xffffffffu,s,o); q += __shfl_xor_sync(0xffffffffu,q,o); }
    float mu = s*(1.f/128.f);
    float inv = rsqrtf(q*(1.f/128.f) - mu*mu + EPSm);
    float x0=(v.x-mu)*inv*lw.x, x1=(v.y-mu)*inv*lw.y;
    float x2=(v.z-mu)*inv*lw.z, x3=(v.w-mu)*inv*lw.w;
    bf16 h0,l0,h1,l1,h2,l2,h3,l3;
    bsplit(x0,h0,l0); bsplit(x1,h1,l1); bsplit(x2,h2,l2); bsplit(x3,h3,l3);
    int base = tok*136 + lane*4;
    __nv_bfloat162 p0; p0.x=h0; p0.y=h1;
    __nv_bfloat162 p1; p1.x=h2; p1.y=h3;
    __nv_bfloat162 q0; q0.x=l0; q0.y=l1;
    __nv_bfloat162 q1; q1.x=l2; q1.y=l3;
    *reinterpret_cast<__nv_bfloat162*>(Ah+base)   = p0;
    *reinterpret_cast<__nv_bfloat162*>(Ah+base+2) = p1;
    *reinterpret_cast<__nv_bfloat162*>(Al+base)   = q0;
    *reinterpret_cast<__nv_bfloat162*>(Al+base+2) = q1;
}
__device__ __forceinline__ void ln_row(const float* __restrict__ hrow, float4 lw, int lane,
                                       bf16* Ah, bf16* Al, int tok){
    float4 v = reinterpret_cast<const float4*>(hrow)[lane];
    ln_core(v, lw, lane, Ah, Al, tok);
}

// ---------------- weight prep ----------------
__global__ void k_prep(const float* __restrict__ wg, const float* __restrict__ wu,
                       const float* __restrict__ wd){
    int id = blockIdx.x*256 + threadIdx.x;   // 131072 total
    if (id < 32768){
        int blk = id >> 14, rem = id & 16383;
        int o = rem >> 5, h = rem & 31;
        int n = o >> 7, r = o & 127, kk = r >> 2, g = r & 3;
        float val = wg[(((blk*4 + g)*4 + n)*32 + kk)*32 + h];
        bf16 hi, lo; bsplit(val, hi, lo);
        g_wgh[id] = hi; g_wgl[id] = lo;
    } else if (id < 98304){
        int t = id - 32768;
        bf16 hi, lo; bsplit(wu[t], hi, lo);
        g_wuh[t] = hi; g_wul[t] = lo;
    } else {
        int t = id - 98304;
        bf16 hi, lo; bsplit(wd[t], hi, lo);
        g_wdh[t] = hi; g_wdl[t] = lo;
    }
}

// ================= block0: fused embed + LN1 + gate GEMM =================
// grid 128, 1024 thr, 256 tokens/CTA. smem el: Ah 0(34816), Al 34816, Wh 69632(512*40), Wl 90112; tot 110592
#define GXS_SMEM (110592*2)
__global__ void __launch_bounds__(1024,1) k_gx0(const int* __restrict__ x, const float* __restrict__ emb,
                                                const float* __restrict__ lnw){
    extern __shared__ bf16 smg[];
    bf16 *Ah = smg, *Al = smg + 34816, *Wh = smg + 69632, *Wl = smg + 90112;
    int tid = threadIdx.x, w = tid>>5, lane = tid&31;
    for (int i = tid; i < 2048; i += 1024){
        int r = i>>2, c8 = (i&3)*8;
        *reinterpret_cast<uint4*>(Wh + r*40 + c8) = *reinterpret_cast<const uint4*>(g_wgh + r*32 + c8);
        *reinterpret_cast<uint4*>(Wl + r*40 + c8) = *reinterpret_cast<const uint4*>(g_wgl + r*32 + c8);
    }
    int t0 = blockIdx.x*256;
    float4 lw = reinterpret_cast<const float4*>(lnw)[lane];
    #pragma unroll 1
    for (int i = 0; i < 8; i++){
        int tok = w*8 + i;
        int t = t0 + tok;
        int v = x[t];
        float4 hv = reinterpret_cast<const float4*>(emb + (size_t)v*128)[lane];
        reinterpret_cast<float4*>(g_h + (size_t)t*128)[lane] = hv;
        ln_core(hv, lw, lane, Ah, Al, tok);
    }
    __syncthreads();

    int gr = lane>>2, gc = (lane&3)*2;
    int r7 = lane&7, g2 = (lane>>3)&1, g4 = lane>>4;
    uint32_t aoff = (uint32_t)(((g2*8 + r7)*136 + g4*8)*2);
    uint32_t boff = (uint32_t)((r7*40 + g2*8)*2);
    uint32_t sAh = s2u(Ah), sAl = s2u(Al), sWh = s2u(Wh), sWl = s2u(Wl);
    int m0 = (w&7)*32;
    int nq = w>>3;                       // head for this warp (0..3)
    #pragma unroll 1
    for (int it = 0; it < 4; it++){
        int nb = nq*128 + it*32;
        float acc[2][4][4];
        #pragma unroll
        for (int ms=0;ms<2;ms++)
            #pragma unroll
            for (int nt=0;nt<4;nt++)
                #pragma unroll
                for (int i=0;i<4;i++) acc[ms][nt][i]=0.f;
        #pragma unroll
        for (int kc = 0; kc < 2; kc++){
            int k0 = nq*32 + kc*16;
            uint32_t ab = (uint32_t)((m0*136 + k0)*2);
            uint32_t ah0[4], ah1[4], al0[4], al1[4];
            ldsm4(ah0, sAh + ab + aoff);
            ldsm4(ah1, sAh + ab + 16u*136u*2u + aoff);
            ldsm4(al0, sAl + ab + aoff);
            ldsm4(al1, sAl + ab + 16u*136u*2u + aoff);
            #pragma unroll
            for (int nt = 0; nt < 4; nt++){
                int nr = nb + nt*8;
                uint32_t bb = (uint32_t)((nr*40 + kc*16)*2) + boff;
                uint32_t bh[2], bl[2];
                ldsm2(bh, sWh + bb);
                ldsm2(bl, sWl + bb);
                mma3(acc[0][nt], ah0, al0, bh, bl);
                mma3(acc[1][nt], ah1, al1, bh, bl);
            }
        }
        #pragma unroll
        for (int ms=0;ms<2;ms++){
            int tA = t0 + m0 + ms*16 + gr;
            int tB = tA + 8;
            int bA = tA>>6, sA = tA&63;
            int bB = tB>>6, sB = tB&63;
            float* dA = &g_gx[((size_t)(sA*Bm + bA))*512];
            float* dB = &g_gx[((size_t)(sB*Bm + bB))*512];
            #pragma unroll
            for (int nt=0;nt<4;nt++){
                int col = nb + nt*8 + gc;
                *reinterpret_cast<float2*>(dA + col) = make_float2(acc[ms][nt][0], acc[ms][nt][1]);
                *reinterpret_cast<float2*>(dB + col) = make_float2(acc[ms][nt][2], acc[ms][nt][3]);
            }
        }
    }
}

// ================= fused LN2 + FF up + GeGLU -> split v =================
#define UPS_SMEM (104448*2)
__global__ void __launch_bounds__(1024,1) k_up(int blk, const float* __restrict__ lnw){
    extern __shared__ bf16 smu[];
    bf16 *Ah = smu, *Al = smu + 17408, *Wh = smu + 34816, *Wl = smu + 69632;
    int tid = threadIdx.x, w = tid>>5, lane = tid&31;
    const bf16* wh = g_wuh + blk*32768;
    const bf16* wl = g_wul + blk*32768;
    for (int i = tid; i < 4096; i += 1024){
        int r = i>>4, c8 = (i&15)*8;
        *reinterpret_cast<uint4*>(Wh + r*136 + c8) = *reinterpret_cast<const uint4*>(wh + r*128 + c8);
        *reinterpret_cast<uint4*>(Wl + r*136 + c8) = *reinterpret_cast<const uint4*>(wl + r*128 + c8);
    }
    float4 lw = reinterpret_cast<const float4*>(lnw)[lane];
    int gr = lane>>2, gc = (lane&3)*2;
    int r7 = lane&7, g2 = (lane>>3)&1, g4 = lane>>4;
    uint32_t aoff = (uint32_t)(((g2*8 + r7)*136 + g4*8)*2);
    uint32_t boff = (uint32_t)((r7*136 + g2*8)*2);
    uint32_t sAh = s2u(Ah), sAl = s2u(Al), sWh = s2u(Wh), sWl = s2u(Wl);
    int m0 = (w&3)*32;
    int j0 = (w>>2)*16;
    #pragma unroll 1
    for (int mt = 0; mt < 2; mt++){
        int t0 = (blockIdx.x*2 + mt)*128;
        __syncthreads();
        #pragma unroll 1
        for (int i = 0; i < 4; i++){
            int tok = w*4 + i;
            ln_row(g_h + (size_t)(t0+tok)*128, lw, lane, Ah, Al, tok);
        }
        __syncthreads();
        float ga[2][2][4], ua[2][2][4];
        #pragma unroll
        for (int ms=0;ms<2;ms++)
            #pragma unroll
            for (int nt=0;nt<2;nt++)
                #pragma unroll
                for (int i=0;i<4;i++){ ga[ms][nt][i]=0.f; ua[ms][nt][i]=0.f; }
        #pragma unroll
        for (int kc = 0; kc < 8; kc++){
            int k0 = kc*16;
            uint32_t ab = (uint32_t)((m0*136 + k0)*2);
            uint32_t ah0[4], ah1[4], al0[4], al1[4];
            ldsm4(ah0, sAh + ab + aoff);
            ldsm4(ah1, sAh + ab + 16u*136u*2u + aoff);
            ldsm4(al0, sAl + ab + aoff);
            ldsm4(al1, sAl + ab + 16u*136u*2u + aoff);
            #pragma unroll
            for (int nt = 0; nt < 2; nt++){
                int jr = j0 + nt*8;
                uint32_t bbg = (uint32_t)((jr*136 + k0)*2) + boff;
                uint32_t bbu = (uint32_t)(((128+jr)*136 + k0)*2) + boff;
                uint32_t bgh[2], bgl[2], buh[2], bul[2];
                ldsm2(bgh, sWh + bbg);
                ldsm2(bgl, sWl + bbg);
                ldsm2(buh, sWh + bbu);
                ldsm2(bul, sWl + bbu);
                mma3(ga[0][nt], ah0, al0, bgh, bgl);
                mma3(ga[1][nt], ah1, al1, bgh, bgl);
                mma3(ua[0][nt], ah0, al0, buh, bul);
                mma3(ua[1][nt], ah1, al1, buh, bul);
            }
        }
        #pragma unroll
        for (int ms=0;ms<2;ms++){
            size_t rA = (size_t)(t0 + m0 + ms*16 + gr)*128;
            size_t rB = rA + 8*128;
            #pragma unroll
            for (int nt=0;nt<2;nt++){
                int col = j0 + nt*8 + gc;
                float v0 = gelu_(ga[ms][nt][0])*ua[ms][nt][0];
                float v1 = gelu_(ga[ms][nt][1])*ua[ms][nt][1];
                float v2 = gelu_(ga[ms][nt][2])*ua[ms][nt][2];
                float v3 = gelu_(ga[ms][nt][3])*ua[ms][nt][3];
                bf16 h0,l0,h1,l1,h2,l2,h3,l3;
                bsplit(v0,h0,l0); bsplit(v1,h1,l1); bsplit(v2,h2,l2); bsplit(v3,h3,l3);
                __nv_bfloat162 p0; p0.x=h0; p0.y=h1;
                __nv_bfloat162 p1; p1.x=h2; p1.y=h3;
                __nv_bfloat162 q0; q0.x=l0; q0.y=l1;
                __nv_bfloat162 q1; q1.x=l2; q1.y=l3;
                *reinterpret_cast<__nv_bfloat162*>(&g_vh[rA + col]) = p0;
                *reinterpret_cast<__nv_bfloat162*>(&g_vh[rB + col]) = p1;
                *reinterpret_cast<__nv_bfloat162*>(&g_vl[rA + col]) = q0;
                *reinterpret_cast<__nv_bfloat162*>(&g_vl[rB + col]) = q1;
            }
        }
    }
}

// ---------------- down-proj core per tile (h updated in g_h) ----------------
__device__ __forceinline__ void down_tile(bf16* Ah, bf16* Al, const bf16* Wh, const bf16* Wl,
                                          int t0, int tid, int w, int lane){
    uint32_t sAh = s2u(Ah), sAl = s2u(Al), sWh = s2u(Wh), sWl = s2u(Wl);
    int gr = lane>>2, gc = (lane&3)*2;
    int r7 = lane&7, g2 = (lane>>3)&1, g4 = lane>>4;
    uint32_t aoff = (uint32_t)(((g2*8 + r7)*136 + g4*8)*2);
    uint32_t boff = (uint32_t)((r7*136 + g2*8)*2);
    int m0 = (w&3)*32;
    int nb = (w>>2)*16;
    for (int i = tid; i < 2048; i += 1024){
        int r = i>>4, c8 = (i&15)*8;
        *reinterpret_cast<uint4*>(Ah + r*136 + c8) = *reinterpret_cast<const uint4*>(g_vh + (size_t)(t0+r)*128 + c8);
        *reinterpret_cast<uint4*>(Al + r*136 + c8) = *reinterpret_cast<const uint4*>(g_vl + (size_t)(t0+r)*128 + c8);
    }
    __syncthreads();
    float acc[2][2][4];
    #pragma unroll
    for (int ms=0;ms<2;ms++)
        #pragma unroll
        for (int nt=0;nt<2;nt++)
            #pragma unroll
            for (int i=0;i<4;i++) acc[ms][nt][i]=0.f;
    #pragma unroll
    for (int kc = 0; kc < 8; kc++){
        int k0 = kc*16;
        uint32_t ab = (uint32_t)((m0*136 + k0)*2);
        uint32_t ah0[4], ah1[4], al0[4], al1[4];
        ldsm4(ah0, sAh + ab + aoff);
        ldsm4(ah1, sAh + ab + 16u*136u*2u + aoff);
        ldsm4(al0, sAl + ab + aoff);
        ldsm4(al1, sAl + ab + 16u*136u*2u + aoff);
        #pragma unroll
        for (int nt = 0; nt < 2; nt++){
            int nr = nb + nt*8;
            uint32_t bb = (uint32_t)((nr*136 + k0)*2) + boff;
            uint32_t bh[2], bl[2];
            ldsm2(bh, sWh + bb);
            ldsm2(bl, sWl + bb);
            mma3(acc[0][nt], ah0, al0, bh, bl);
            mma3(acc[1][nt], ah1, al1, bh, bl);
        }
    }
    #pragma unroll
    for (int ms=0;ms<2;ms++){
        size_t rA = (size_t)(t0 + m0 + ms*16 + gr)*128;
        size_t rB = rA + 8*128;
        #pragma unroll
        for (int nt=0;nt<2;nt++){
            int col = nb + nt*8 + gc;
            float2* pA = reinterpret_cast<float2*>(&g_h[rA + col]);
            float2* pB = reinterpret_cast<float2*>(&g_h[rB + col]);
            float2 hA = *pA, hB = *pB;
            hA.x += acc[ms][nt][0]; hA.y += acc[ms][nt][1];
            hB.x += acc[ms][nt][2]; hB.y += acc[ms][nt][3];
            *pA = hA; *pB = hB;
        }
    }
}

// ================= fused FF-down(blk0) + LN1 + gate-GEMM(blk1) =================
// grid 128, 1024 thr, 2 x 128-token tiles
// smem el: Ah 0(17408), Al 17408, Wdh 34816(17408), Wdl 52224, Wgh 69632(512*40=20480), Wgl 90112; tot 110592
#define DGX_SMEM (110592*2)
__global__ void __launch_bounds__(1024,1) k_downgx(const float* __restrict__ lnw){
    extern __shared__ bf16 smd[];
    bf16 *Ah = smd, *Al = smd + 17408, *Wdh = smd + 34816, *Wdl = smd + 52224;
    bf16 *Wgh = smd + 69632, *Wgl = smd + 90112;
    int tid = threadIdx.x, w = tid>>5, lane = tid&31;
    for (int i = tid; i < 2048; i += 1024){
        int r = i>>4, c8 = (i&15)*8;
        *reinterpret_cast<uint4*>(Wdh + r*136 + c8) = *reinterpret_cast<const uint4*>(g_wdh + r*128 + c8);
        *reinterpret_cast<uint4*>(Wdl + r*136 + c8) = *reinterpret_cast<const uint4*>(g_wdl + r*128 + c8);
    }
    for (int i = tid; i < 2048; i += 1024){
        int r = i>>2, c8 = (i&3)*8;
        *reinterpret_cast<uint4*>(Wgh + r*40 + c8) = *reinterpret_cast<const uint4*>(g_wgh + 16384 + r*32 + c8);
        *reinterpret_cast<uint4*>(Wgl + r*40 + c8) = *reinterpret_cast<const uint4*>(g_wgl + 16384 + r*32 + c8);
    }
    float4 lw = reinterpret_cast<const float4*>(lnw)[lane];
    int gr = lane>>2, gc = (lane&3)*2;
    int r7 = lane&7, g2 = (lane>>3)&1, g4 = lane>>4;
    uint32_t aoff = (uint32_t)(((g2*8 + r7)*136 + g4*8)*2);
    uint32_t boffg = (uint32_t)((r7*40 + g2*8)*2);
    uint32_t sAh = s2u(Ah), sAl = s2u(Al), sWgh = s2u(Wgh), sWgl = s2u(Wgl);
    #pragma unroll 1
    for (int mt = 0; mt < 2; mt++){
        int t0 = (blockIdx.x*2 + mt)*128;
        __syncthreads();
        down_tile(Ah, Al, Wdh, Wdl, t0, tid, w, lane);
        __syncthreads();        // all h rows of tile updated in g_h
        // LN1(blk1) into Ah/Al (overwrite V)
        #pragma unroll 1
        for (int i = 0; i < 4; i++){
            int tok = w*4 + i;
            ln_row(g_h + (size_t)(t0+tok)*128, lw, lane, Ah, Al, tok);
        }
        __syncthreads();
        // gate GEMM: m-split 4, n-split 8, 2 passes
        int m0 = (w&3)*32;
        int nqq = w>>2;                   // 0..7
        #pragma unroll 1
        for (int p = 0; p < 2; p++){
            int nb = p*256 + nqq*32;
            int head = nb >> 7;
            float acc[2][4][4];
            #pragma unroll
            for (int ms=0;ms<2;ms++)
                #pragma unroll
                for (int nt=0;nt<4;nt++)
                    #pragma unroll
                    for (int i=0;i<4;i++) acc[ms][nt][i]=0.f;
            #pragma unroll
            for (int kc = 0; kc < 2; kc++){
                int k0 = head*32 + kc*16;
                uint32_t ab = (uint32_t)((m0*136 + k0)*2);
                uint32_t ah0[4], ah1[4], al0[4], al1[4];
                ldsm4(ah0, sAh + ab + aoff);
                ldsm4(ah1, sAh + ab + 16u*136u*2u + aoff);
                ldsm4(al0, sAl + ab + aoff);
                ldsm4(al1, sAl + ab + 16u*136u*2u + aoff);
                #pragma unroll
                for (int nt = 0; nt < 4; nt++){
                    int nr = nb + nt*8;
                    uint32_t bb = (uint32_t)((nr*40 + kc*16)*2) + boffg;
                    uint32_t bh[2], bl[2];
                    ldsm2(bh, sWgh + bb);
                    ldsm2(bl, sWgl + bb);
                    mma3(acc[0][nt], ah0, al0, bh, bl);
                    mma3(acc[1][nt], ah1, al1, bh, bl);
                }
            }
            #pragma unroll
            for (int ms=0;ms<2;ms++){
                int tA = t0 + m0 + ms*16 + gr;
                int tB = tA + 8;
                int bA = tA>>6, sA = tA&63;
                int bB = tB>>6, sB = tB&63;
                float* dA = &g_gx[((size_t)(sA*Bm + bA))*512];
                float* dB = &g_gx[((size_t)(sB*Bm + bB))*512];
                #pragma unroll
                for (int nt=0;nt<4;nt++){
                    int col = nb + nt*8 + gc;
                    *reinterpret_cast<float2*>(dA + col) = make_float2(acc[ms][nt][0], acc[ms][nt][1]);
                    *reinterpret_cast<float2*>(dB + col) = make_float2(acc[ms][nt][2], acc[ms][nt][3]);
                }
            }
        }
    }
}

// ================= fused FF-down(blk1) + final LN + projection =================
#define DNP_SMEM (69632*2)
__global__ void __launch_bounds__(1024,1) k_downproj(const float* __restrict__ pw_ln,
                                                     const float* __restrict__ pjw,
                                                     const float* __restrict__ pjb,
                                                     float* __restrict__ out){
    extern __shared__ bf16 smp[];
    bf16 *Ah = smp, *Al = smp + 17408, *Wdh = smp + 34816, *Wdl = smp + 52224;
    int tid = threadIdx.x, w = tid>>5, lane = tid&31;
    for (int i = tid; i < 2048; i += 1024){
        int r = i>>4, c8 = (i&15)*8;
        *reinterpret_cast<uint4*>(Wdh + r*136 + c8) = *reinterpret_cast<const uint4*>(g_wdh + 16384 + r*128 + c8);
        *reinterpret_cast<uint4*>(Wdl + r*136 + c8) = *reinterpret_cast<const uint4*>(g_wdl + 16384 + r*128 + c8);
    }
    float4 pw = reinterpret_cast<const float4*>(pw_ln)[lane];
    #pragma unroll 1
    for (int mt = 0; mt < 2; mt++){
        int t0 = (blockIdx.x*2 + mt)*128;
        __syncthreads();
        down_tile(Ah, Al, Wdh, Wdl, t0, tid, w, lane);
        __syncthreads();
        // final LN + 9-way projection, warp per token x4
        #pragma unroll 1
        for (int i = 0; i < 4; i++){
            int t = t0 + w*4 + i;
            float4 v = reinterpret_cast<const float4*>(g_h + (size_t)t*128)[lane];
            float s = v.x+v.y+v.z+v.w;
            float q = v.x*v.x+v.y*v.y+v.z*v.z+v.w*v.w;
            #pragma unroll
            for (int o=16;o>0;o>>=1){ s += __shfl_xor_sync(0xffffffffu,s,o); q += __shfl_xor_sync(0xffffffffu,q,o); }
            float mu = s*(1.f/128.f);
            float inv = rsqrtf(q*(1.f/128.f) - mu*mu + EPSm);
            float4 xv;
            xv.x=(v.x-mu)*inv*pw.x; xv.y=(v.y-mu)*inv*pw.y;
            xv.z=(v.z-mu)*inv*pw.z; xv.w=(v.w-mu)*inv*pw.w;
            float res = 0.f;
            #pragma unroll
            for (int vc = 0; vc < 9; vc++){
                float4 p = reinterpret_cast<const float4*>(pjw + vc*Dm)[lane];
                float sv = xv.x*p.x + xv.y*p.y + xv.z*p.z + xv.w*p.w;
                #pragma unroll
                for (int o=16;o>0;o>>=1) sv += __shfl_xor_sync(0xffffffffu,sv,o);
                if (lane == vc) res = sv;
            }
            if (lane < 9) out[t*9 + lane] = res + pjb[lane];
        }
    }
}

// ---------------- sLSTM gate math (branchless) ----------------
__device__ __forceinline__ float slstm_step(float i_r, float f_r, float z_r, float o_r,
                                            float& c, float& nn, float& m){
    float lsf = fminf(f_r, 0.f) - __logf(1.f + __expf(-fabsf(f_r)));
    float lfm = m + lsf;
    float mnew = fmaxf(i_r, lfm);
    float ig = __expf(i_r - mnew);
    float fg = __expf(lfm - mnew);
    float e2z = __expf(2.f*z_r);
    float tz = 1.f - __fdividef(2.f, e2z + 1.f);
    c  = fg*c  + ig*tz;
    nn = fg*nn + ig;
    m  = mnew;
    float so = __fdividef(1.f, 1.f + __expf(-o_r));
    return so * __fdividef(c, nn);
}

// ================= sequential scan: 1 batch/CTA, grid 512 =================
__global__ void __launch_bounds__(128,3) k_scan(const float* __restrict__ Rw,
                                                const float* __restrict__ bw,
                                                const float* __restrict__ gnw){
    __shared__ __align__(16) float hs[1024];   // [buf][o*2]
    int tid = threadIdx.x;
    int n = tid >> 5, k = tid & 31;
    int b = blockIdx.x;

    ull r01[32], r23[32];
    const float* rp = Rw + n*4096 + k;
    #pragma unroll
    for (int h = 0; h < 32; h++){
        r01[h] = pk2(rp[h*128],      rp[h*128 + 32]);
        r23[h] = pk2(rp[h*128 + 64], rp[h*128 + 96]);
    }
    float bias0 = bw[(n*4+0)*32+k], bias1 = bw[(n*4+1)*32+k];
    float bias2 = bw[(n*4+2)*32+k], bias3 = bw[(n*4+3)*32+k];
    float gw = gnw[n*32+k];

    int o = n*32 + k;
    *reinterpret_cast<ull*>(&hs[o*2]) = 0ull;
    float ca=0.f, na=0.f, ma=0.f;
    __syncwarp();

    const float4* pga = reinterpret_cast<const float4*>(&g_gx[(size_t)b*512 + o*4]);
    float* hp = &g_h[(size_t)(b*64)*Dm + o];
    float4 ga = pga[0];
    int cur = 0;

    for (int s = 0; s < Sm; s++){
        float hres = hp[s*Dm];
        float4 gan = ga;
        if (s < Sm-1) gan = pga[(s+1)*65536];
        ull a0e=0,a0o=0,a1e=0,a1o=0;
        const ulonglong2* hv = reinterpret_cast<const ulonglong2*>(&hs[cur*512 + n*64]);
        #pragma unroll
        for (int hh = 0; hh < 16; hh++){
            ulonglong2 ha = hv[hh];
            a0e = fma2_(ha.x, r01[2*hh],   a0e);
            a1e = fma2_(ha.x, r23[2*hh],   a1e);
            a0o = fma2_(ha.y, r01[2*hh+1], a0o);
            a1o = fma2_(ha.y, r23[2*hh+1], a1o);
        }
        ull aa01 = add2_(a0e, a0o);
        ull aa23 = add2_(a1e, a1o);
        float ria,rfa,rza,roa;
        upk2(aa01,ria,rfa); upk2(aa23,rza,roa);
        float hn = slstm_step(ria+ga.x+bias0, rfa+ga.y+bias1, rza+ga.z+bias2, roa+ga.w+bias3, ca,na,ma);
        int nxt = cur ^ 1;
        *reinterpret_cast<ull*>(&hs[nxt*512 + o*2]) = pk2(hn, hn);
        __syncwarp();
        float sa = hn, qa = hn*hn;
        #pragma unroll
        for (int off=16; off>0; off>>=1){
            sa += __shfl_xor_sync(0xffffffffu,sa,off);
            qa += __shfl_xor_sync(0xffffffffu,qa,off);
        }
        float mua = sa*(1.f/32.f);
        float inva = rsqrtf(qa*(1.f/32.f) - mua*mua + EPSm);
        hp[s*Dm] = hres + (hn - mua)*inva*gw;
        ga = gan;
        cur = nxt;
    }
}

// ---------------- launch ----------------
extern "C" void kernel_launch(void* const* d_in, const int* in_sizes, int n_in,
                              void* d_out, int out_size){
    const int*   x      = (const int*)  d_in[0];
    const float* emb    = (const float*)d_in[1];
    const float* ln1_w  = (const float*)d_in[2];
    const float* Wg     = (const float*)d_in[3];
    const float* R      = (const float*)d_in[4];
    const float* bias   = (const float*)d_in[5];
    const float* gn_w   = (const float*)d_in[6];
    const float* ln2_w  = (const float*)d_in[7];
    const float* ffu    = (const float*)d_in[8];
    const float* ffd    = (const float*)d_in[9];
    const float* post_w = (const float*)d_in[10];
    const float* pjw    = (const float*)d_in[11];
    const float* pjb    = (const float*)d_in[12];
    float* out = (float*)d_out;

    cudaFuncSetAttribute(k_gx0,     cudaFuncAttributeMaxDynamicSharedMemorySize, GXS_SMEM);
    cudaFuncSetAttribute(k_up,      cudaFuncAttributeMaxDynamicSharedMemorySize, UPS_SMEM);
    cudaFuncSetAttribute(k_downgx,  cudaFuncAttributeMaxDynamicSharedMemorySize, DGX_SMEM);
    cudaFuncSetAttribute(k_downproj,cudaFuncAttributeMaxDynamicSharedMemorySize, DNP_SMEM);

    k_prep    <<<512,256>>>(Wg, ffu, ffd);
    k_gx0     <<<128,1024,GXS_SMEM>>>(x, emb, ln1_w);
    k_scan    <<<512,128>>>(R, bias, gn_w);
    k_up      <<<128,1024,UPS_SMEM>>>(0, ln2_w);
    k_downgx  <<<128,1024,DGX_SMEM>>>(ln1_w + Dm);
    k_scan    <<<512,128>>>(R + 16384, bias + 512, gn_w + Dm);
    k_up      <<<128,1024,UPS_SMEM>>>(1, ln2_w + Dm);
    k_downproj<<<128,1024,DNP_SMEM>>>(post_w, pjw, pjb, out);
}

// round 17
// speedup vs baseline: 1.8091x; 1.8091x over previous
#include <cuda_runtime.h>
#include <cuda_bf16.h>
#include <math.h>
#include <stdint.h>
#include <cstdint>

#define Bm 512
#define Sm 64
#define Dm 128
#define EPSm 1e-5f
typedef unsigned long long ull;
typedef __nv_bfloat16 bf16;

// ---------------- scratch ----------------
__device__ float g_h[Bm*Sm*Dm];
__device__ float g_gx[(size_t)Sm*Bm*512];
__device__ __align__(16) bf16 g_vh[Bm*Sm*Dm], g_vl[Bm*Sm*Dm];
__device__ __align__(16) bf16 g_wgh[2*512*32],  g_wgl[2*512*32];   // [blk][o][h]
__device__ __align__(16) bf16 g_wuh[2*256*128], g_wul[2*256*128];
__device__ __align__(16) bf16 g_wdh[2*128*128], g_wdl[2*128*128];

// ---------------- f32x2 helpers ----------------
__device__ __forceinline__ ull pk2(float a, float b){ ull r; asm("mov.b64 %0, {%1,%2};" : "=l"(r) : "f"(a), "f"(b)); return r; }
__device__ __forceinline__ void upk2(ull v, float &a, float &b){ asm("mov.b64 {%0,%1}, %2;" : "=f"(a), "=f"(b) : "l"(v)); }
__device__ __forceinline__ ull fma2_(ull a, ull b, ull c){ ull d; asm("fma.rn.f32x2 %0, %1, %2, %3;" : "=l"(d) : "l"(a), "l"(b), "l"(c)); return d; }
__device__ __forceinline__ ull add2_(ull a, ull b){ ull d; asm("add.rn.f32x2 %0, %1, %2;" : "=l"(d) : "l"(a), "l"(b)); return d; }

// ---------------- mma helpers ----------------
__device__ __forceinline__ uint32_t s2u(const void* p){ return (uint32_t)__cvta_generic_to_shared(p); }
__device__ __forceinline__ void mma_bf16(float* c, const uint32_t* a, const uint32_t* b){
    asm("mma.sync.aligned.m16n8k16.row.col.f32.bf16.bf16.f32 "
        "{%0,%1,%2,%3}, {%4,%5,%6,%7}, {%8,%9}, {%0,%1,%2,%3};"
        : "+f"(c[0]), "+f"(c[1]), "+f"(c[2]), "+f"(c[3])
        : "r"(a[0]), "r"(a[1]), "r"(a[2]), "r"(a[3]), "r"(b[0]), "r"(b[1]));
}
__device__ __forceinline__ void ldsm4(uint32_t* r, uint32_t addr){
    asm volatile("ldmatrix.sync.aligned.m8n8.x4.shared.b16 {%0,%1,%2,%3}, [%4];"
        : "=r"(r[0]),"=r"(r[1]),"=r"(r[2]),"=r"(r[3]) : "r"(addr));
}
__device__ __forceinline__ void ldsm2(uint32_t* r, uint32_t addr){
    asm volatile("ldmatrix.sync.aligned.m8n8.x2.shared.b16 {%0,%1}, [%2];"
        : "=r"(r[0]),"=r"(r[1]) : "r"(addr));
}
__device__ __forceinline__ void mma3(float* c, const uint32_t* ah, const uint32_t* al,
                                     const uint32_t* bh, const uint32_t* bl){
    mma_bf16(c, ah, bh);
    mma_bf16(c, ah, bl);
    mma_bf16(c, al, bh);
}
__device__ __forceinline__ void bsplit(float x, bf16& h, bf16& l){
    h = __float2bfloat16(x);
    l = __float2bfloat16(x - __bfloat162float(h));
}
__device__ __forceinline__ float gelu_(float g){
    return 0.5f*g*(1.f + erff(g*0.70710678118f));
}

// LN one token -> split bf16 into padded smem row (stride 136)
__device__ __forceinline__ void ln_core(float4 v, float4 lw, int lane, bf16* Ah, bf16* Al, int tok){
    float s = v.x+v.y+v.z+v.w;
    float q = v.x*v.x+v.y*v.y+v.z*v.z+v.w*v.w;
    #pragma unroll
    for (int o=16;o>0;o>>=1){ s += __shfl_xor_sync(0xffffffffu,s,o); q += __shfl_xor_sync(0xffffffffu,q,o); }
    float mu = s*(1.f/128.f);
    float inv = rsqrtf(q*(1.f/128.f) - mu*mu + EPSm);
    float x0=(v.x-mu)*inv*lw.x, x1=(v.y-mu)*inv*lw.y;
    float x2=(v.z-mu)*inv*lw.z, x3=(v.w-mu)*inv*lw.w;
    bf16 h0,l0,h1,l1,h2,l2,h3,l3;
    bsplit(x0,h0,l0); bsplit(x1,h1,l1); bsplit(x2,h2,l2); bsplit(x3,h3,l3);
    int base = tok*136 + lane*4;
    __nv_bfloat162 p0; p0.x=h0; p0.y=h1;
    __nv_bfloat162 p1; p1.x=h2; p1.y=h3;
    __nv_bfloat162 q0; q0.x=l0; q0.y=l1;
    __nv_bfloat162 q1; q1.x=l2; q1.y=l3;
    *reinterpret_cast<__nv_bfloat162*>(Ah+base)   = p0;
    *reinterpret_cast<__nv_bfloat162*>(Ah+base+2) = p1;
    *reinterpret_cast<__nv_bfloat162*>(Al+base)   = q0;
    *reinterpret_cast<__nv_bfloat162*>(Al+base+2) = q1;
}
__device__ __forceinline__ void ln_row(const float* __restrict__ hrow, float4 lw, int lane,
                                       bf16* Ah, bf16* Al, int tok){
    float4 v = reinterpret_cast<const float4*>(hrow)[lane];
    ln_core(v, lw, lane, Ah, Al, tok);
}

// ---------------- weight prep ----------------
__global__ void k_prep(const float* __restrict__ wg, const float* __restrict__ wu,
                       const float* __restrict__ wd){
    int id = blockIdx.x*256 + threadIdx.x;   // 131072 total
    if (id < 32768){
        int blk = id >> 14, rem = id & 16383;
        int o = rem >> 5, h = rem & 31;
        int n = o >> 7, r = o & 127, kk = r >> 2, g = r & 3;
        float val = wg[(((blk*4 + g)*4 + n)*32 + kk)*32 + h];
        bf16 hi, lo; bsplit(val, hi, lo);
        g_wgh[id] = hi; g_wgl[id] = lo;
    } else if (id < 98304){
        int t = id - 32768;
        bf16 hi, lo; bsplit(wu[t], hi, lo);
        g_wuh[t] = hi; g_wul[t] = lo;
    } else {
        int t = id - 98304;
        bf16 hi, lo; bsplit(wd[t], hi, lo);
        g_wdh[t] = hi; g_wdl[t] = lo;
    }
}

// ================= block0: fused embed + LN1 + gate GEMM =================
// grid 128, 1024 thr, 256 tokens/CTA. smem el: Ah 0(34816), Al 34816, Wh 69632(512*40), Wl 90112; tot 110592
#define GXS_SMEM (110592*2)
__global__ void __launch_bounds__(1024,1) k_gx0(const int* __restrict__ x, const float* __restrict__ emb,
                                                const float* __restrict__ lnw){
    extern __shared__ bf16 smg[];
    bf16 *Ah = smg, *Al = smg + 34816, *Wh = smg + 69632, *Wl = smg + 90112;
    int tid = threadIdx.x, w = tid>>5, lane = tid&31;
    for (int i = tid; i < 2048; i += 1024){
        int r = i>>2, c8 = (i&3)*8;
        *reinterpret_cast<uint4*>(Wh + r*40 + c8) = *reinterpret_cast<const uint4*>(g_wgh + r*32 + c8);
        *reinterpret_cast<uint4*>(Wl + r*40 + c8) = *reinterpret_cast<const uint4*>(g_wgl + r*32 + c8);
    }
    int t0 = blockIdx.x*256;
    float4 lw = reinterpret_cast<const float4*>(lnw)[lane];
    #pragma unroll 1
    for (int i = 0; i < 8; i++){
        int tok = w*8 + i;
        int t = t0 + tok;
        int v = x[t];
        float4 hv = reinterpret_cast<const float4*>(emb + (size_t)v*128)[lane];
        reinterpret_cast<float4*>(g_h + (size_t)t*128)[lane] = hv;
        ln_core(hv, lw, lane, Ah, Al, tok);
    }
    __syncthreads();

    int gr = lane>>2, gc = (lane&3)*2;
    int r7 = lane&7, g2 = (lane>>3)&1, g4 = lane>>4;
    uint32_t aoff = (uint32_t)(((g2*8 + r7)*136 + g4*8)*2);
    uint32_t boff = (uint32_t)((r7*40 + g2*8)*2);
    uint32_t sAh = s2u(Ah), sAl = s2u(Al), sWh = s2u(Wh), sWl = s2u(Wl);
    int m0 = (w&7)*32;
    int nq = w>>3;                       // head for this warp (0..3)
    #pragma unroll 1
    for (int it = 0; it < 4; it++){
        int nb = nq*128 + it*32;
        float acc[2][4][4];
        #pragma unroll
        for (int ms=0;ms<2;ms++)
            #pragma unroll
            for (int nt=0;nt<4;nt++)
                #pragma unroll
                for (int i=0;i<4;i++) acc[ms][nt][i]=0.f;
        #pragma unroll
        for (int kc = 0; kc < 2; kc++){
            int k0 = nq*32 + kc*16;
            uint32_t ab = (uint32_t)((m0*136 + k0)*2);
            uint32_t ah0[4], ah1[4], al0[4], al1[4];
            ldsm4(ah0, sAh + ab + aoff);
            ldsm4(ah1, sAh + ab + 16u*136u*2u + aoff);
            ldsm4(al0, sAl + ab + aoff);
            ldsm4(al1, sAl + ab + 16u*136u*2u + aoff);
            #pragma unroll
            for (int nt = 0; nt < 4; nt++){
                int nr = nb + nt*8;
                uint32_t bb = (uint32_t)((nr*40 + kc*16)*2) + boff;
                uint32_t bh[2], bl[2];
                ldsm2(bh, sWh + bb);
                ldsm2(bl, sWl + bb);
                mma3(acc[0][nt], ah0, al0, bh, bl);
                mma3(acc[1][nt], ah1, al1, bh, bl);
            }
        }
        #pragma unroll
        for (int ms=0;ms<2;ms++){
            int tA = t0 + m0 + ms*16 + gr;
            int tB = tA + 8;
            int bA = tA>>6, sA = tA&63;
            int bB = tB>>6, sB = tB&63;
            float* dA = &g_gx[((size_t)(sA*Bm + bA))*512];
            float* dB = &g_gx[((size_t)(sB*Bm + bB))*512];
            #pragma unroll
            for (int nt=0;nt<4;nt++){
                int col = nb + nt*8 + gc;
                *reinterpret_cast<float2*>(dA + col) = make_float2(acc[ms][nt][0], acc[ms][nt][1]);
                *reinterpret_cast<float2*>(dB + col) = make_float2(acc[ms][nt][2], acc[ms][nt][3]);
            }
        }
    }
}

// ================= fused LN2 + FF up + GeGLU -> split v =================
#define UPS_SMEM (104448*2)
__global__ void __launch_bounds__(1024,1) k_up(int blk, const float* __restrict__ lnw){
    extern __shared__ bf16 smu[];
    bf16 *Ah = smu, *Al = smu + 17408, *Wh = smu + 34816, *Wl = smu + 69632;
    int tid = threadIdx.x, w = tid>>5, lane = tid&31;
    const bf16* wh = g_wuh + blk*32768;
    const bf16* wl = g_wul + blk*32768;
    for (int i = tid; i < 4096; i += 1024){
        int r = i>>4, c8 = (i&15)*8;
        *reinterpret_cast<uint4*>(Wh + r*136 + c8) = *reinterpret_cast<const uint4*>(wh + r*128 + c8);
        *reinterpret_cast<uint4*>(Wl + r*136 + c8) = *reinterpret_cast<const uint4*>(wl + r*128 + c8);
    }
    float4 lw = reinterpret_cast<const float4*>(lnw)[lane];
    int gr = lane>>2, gc = (lane&3)*2;
    int r7 = lane&7, g2 = (lane>>3)&1, g4 = lane>>4;
    uint32_t aoff = (uint32_t)(((g2*8 + r7)*136 + g4*8)*2);
    uint32_t boff = (uint32_t)((r7*136 + g2*8)*2);
    uint32_t sAh = s2u(Ah), sAl = s2u(Al), sWh = s2u(Wh), sWl = s2u(Wl);
    int m0 = (w&3)*32;
    int j0 = (w>>2)*16;
    #pragma unroll 1
    for (int mt = 0; mt < 2; mt++){
        int t0 = (blockIdx.x*2 + mt)*128;
        __syncthreads();
        #pragma unroll 1
        for (int i = 0; i < 4; i++){
            int tok = w*4 + i;
            ln_row(g_h + (size_t)(t0+tok)*128, lw, lane, Ah, Al, tok);
        }
        __syncthreads();
        float ga[2][2][4], ua[2][2][4];
        #pragma unroll
        for (int ms=0;ms<2;ms++)
            #pragma unroll
            for (int nt=0;nt<2;nt++)
                #pragma unroll
                for (int i=0;i<4;i++){ ga[ms][nt][i]=0.f; ua[ms][nt][i]=0.f; }
        #pragma unroll
        for (int kc = 0; kc < 8; kc++){
            int k0 = kc*16;
            uint32_t ab = (uint32_t)((m0*136 + k0)*2);
            uint32_t ah0[4], ah1[4], al0[4], al1[4];
            ldsm4(ah0, sAh + ab + aoff);
            ldsm4(ah1, sAh + ab + 16u*136u*2u + aoff);
            ldsm4(al0, sAl + ab + aoff);
            ldsm4(al1, sAl + ab + 16u*136u*2u + aoff);
            #pragma unroll
            for (int nt = 0; nt < 2; nt++){
                int jr = j0 + nt*8;
                uint32_t bbg = (uint32_t)((jr*136 + k0)*2) + boff;
                uint32_t bbu = (uint32_t)(((128+jr)*136 + k0)*2) + boff;
                uint32_t bgh[2], bgl[2], buh[2], bul[2];
                ldsm2(bgh, sWh + bbg);
                ldsm2(bgl, sWl + bbg);
                ldsm2(buh, sWh + bbu);
                ldsm2(bul, sWl + bbu);
                mma3(ga[0][nt], ah0, al0, bgh, bgl);
                mma3(ga[1][nt], ah1, al1, bgh, bgl);
                mma3(ua[0][nt], ah0, al0, buh, bul);
                mma3(ua[1][nt], ah1, al1, buh, bul);
            }
        }
        #pragma unroll
        for (int ms=0;ms<2;ms++){
            size_t rA = (size_t)(t0 + m0 + ms*16 + gr)*128;
            size_t rB = rA + 8*128;
            #pragma unroll
            for (int nt=0;nt<2;nt++){
                int col = j0 + nt*8 + gc;
                float v0 = gelu_(ga[ms][nt][0])*ua[ms][nt][0];
                float v1 = gelu_(ga[ms][nt][1])*ua[ms][nt][1];
                float v2 = gelu_(ga[ms][nt][2])*ua[ms][nt][2];
                float v3 = gelu_(ga[ms][nt][3])*ua[ms][nt][3];
                bf16 h0,l0,h1,l1,h2,l2,h3,l3;
                bsplit(v0,h0,l0); bsplit(v1,h1,l1); bsplit(v2,h2,l2); bsplit(v3,h3,l3);
                __nv_bfloat162 p0; p0.x=h0; p0.y=h1;
                __nv_bfloat162 p1; p1.x=h2; p1.y=h3;
                __nv_bfloat162 q0; q0.x=l0; q0.y=l1;
                __nv_bfloat162 q1; q1.x=l2; q1.y=l3;
                *reinterpret_cast<__nv_bfloat162*>(&g_vh[rA + col]) = p0;
                *reinterpret_cast<__nv_bfloat162*>(&g_vh[rB + col]) = p1;
                *reinterpret_cast<__nv_bfloat162*>(&g_vl[rA + col]) = q0;
                *reinterpret_cast<__nv_bfloat162*>(&g_vl[rB + col]) = q1;
            }
        }
    }
}

// ---------------- down-proj core per tile (h updated in g_h) ----------------
__device__ __forceinline__ void down_tile(bf16* Ah, bf16* Al, const bf16* Wh, const bf16* Wl,
                                          int t0, int tid, int w, int lane){
    uint32_t sAh = s2u(Ah), sAl = s2u(Al), sWh = s2u(Wh), sWl = s2u(Wl);
    int gr = lane>>2, gc = (lane&3)*2;
    int r7 = lane&7, g2 = (lane>>3)&1, g4 = lane>>4;
    uint32_t aoff = (uint32_t)(((g2*8 + r7)*136 + g4*8)*2);
    uint32_t boff = (uint32_t)((r7*136 + g2*8)*2);
    int m0 = (w&3)*32;
    int nb = (w>>2)*16;
    for (int i = tid; i < 2048; i += 1024){
        int r = i>>4, c8 = (i&15)*8;
        *reinterpret_cast<uint4*>(Ah + r*136 + c8) = *reinterpret_cast<const uint4*>(g_vh + (size_t)(t0+r)*128 + c8);
        *reinterpret_cast<uint4*>(Al + r*136 + c8) = *reinterpret_cast<const uint4*>(g_vl + (size_t)(t0+r)*128 + c8);
    }
    __syncthreads();
    float acc[2][2][4];
    #pragma unroll
    for (int ms=0;ms<2;ms++)
        #pragma unroll
        for (int nt=0;nt<2;nt++)
            #pragma unroll
            for (int i=0;i<4;i++) acc[ms][nt][i]=0.f;
    #pragma unroll
    for (int kc = 0; kc < 8; kc++){
        int k0 = kc*16;
        uint32_t ab = (uint32_t)((m0*136 + k0)*2);
        uint32_t ah0[4], ah1[4], al0[4], al1[4];
        ldsm4(ah0, sAh + ab + aoff);
        ldsm4(ah1, sAh + ab + 16u*136u*2u + aoff);
        ldsm4(al0, sAl + ab + aoff);
        ldsm4(al1, sAl + ab + 16u*136u*2u + aoff);
        #pragma unroll
        for (int nt = 0; nt < 2; nt++){
            int nr = nb + nt*8;
            uint32_t bb = (uint32_t)((nr*136 + k0)*2) + boff;
            uint32_t bh[2], bl[2];
            ldsm2(bh, sWh + bb);
            ldsm2(bl, sWl + bb);
            mma3(acc[0][nt], ah0, al0, bh, bl);
            mma3(acc[1][nt], ah1, al1, bh, bl);
        }
    }
    #pragma unroll
    for (int ms=0;ms<2;ms++){
        size_t rA = (size_t)(t0 + m0 + ms*16 + gr)*128;
        size_t rB = rA + 8*128;
        #pragma unroll
        for (int nt=0;nt<2;nt++){
            int col = nb + nt*8 + gc;
            float2* pA = reinterpret_cast<float2*>(&g_h[rA + col]);
            float2* pB = reinterpret_cast<float2*>(&g_h[rB + col]);
            float2 hA = *pA, hB = *pB;
            hA.x += acc[ms][nt][0]; hA.y += acc[ms][nt][1];
            hB.x += acc[ms][nt][2]; hB.y += acc[ms][nt][3];
            *pA = hA; *pB = hB;
        }
    }
}

// ================= fused FF-down(blk0) + LN1 + gate-GEMM(blk1) =================
// grid 128, 1024 thr, 2 x 128-token tiles
#define DGX_SMEM (110592*2)
__global__ void __launch_bounds__(1024,1) k_downgx(const float* __restrict__ lnw){
    extern __shared__ bf16 smd[];
    bf16 *Ah = smd, *Al = smd + 17408, *Wdh = smd + 34816, *Wdl = smd + 52224;
    bf16 *Wgh = smd + 69632, *Wgl = smd + 90112;
    int tid = threadIdx.x, w = tid>>5, lane = tid&31;
    for (int i = tid; i < 2048; i += 1024){
        int r = i>>4, c8 = (i&15)*8;
        *reinterpret_cast<uint4*>(Wdh + r*136 + c8) = *reinterpret_cast<const uint4*>(g_wdh + r*128 + c8);
        *reinterpret_cast<uint4*>(Wdl + r*136 + c8) = *reinterpret_cast<const uint4*>(g_wdl + r*128 + c8);
    }
    for (int i = tid; i < 2048; i += 1024){
        int r = i>>2, c8 = (i&3)*8;
        *reinterpret_cast<uint4*>(Wgh + r*40 + c8) = *reinterpret_cast<const uint4*>(g_wgh + 16384 + r*32 + c8);
        *reinterpret_cast<uint4*>(Wgl + r*40 + c8) = *reinterpret_cast<const uint4*>(g_wgl + 16384 + r*32 + c8);
    }
    float4 lw = reinterpret_cast<const float4*>(lnw)[lane];
    int gr = lane>>2, gc = (lane&3)*2;
    int r7 = lane&7, g2 = (lane>>3)&1, g4 = lane>>4;
    uint32_t aoff = (uint32_t)(((g2*8 + r7)*136 + g4*8)*2);
    uint32_t boffg = (uint32_t)((r7*40 + g2*8)*2);
    uint32_t sAh = s2u(Ah), sAl = s2u(Al), sWgh = s2u(Wgh), sWgl = s2u(Wgl);
    #pragma unroll 1
    for (int mt = 0; mt < 2; mt++){
        int t0 = (blockIdx.x*2 + mt)*128;
        __syncthreads();
        down_tile(Ah, Al, Wdh, Wdl, t0, tid, w, lane);
        __syncthreads();        // all h rows of tile updated in g_h
        #pragma unroll 1
        for (int i = 0; i < 4; i++){
            int tok = w*4 + i;
            ln_row(g_h + (size_t)(t0+tok)*128, lw, lane, Ah, Al, tok);
        }
        __syncthreads();
        int m0 = (w&3)*32;
        int nqq = w>>2;                   // 0..7
        #pragma unroll 1
        for (int p = 0; p < 2; p++){
            int nb = p*256 + nqq*32;
            int head = nb >> 7;
            float acc[2][4][4];
            #pragma unroll
            for (int ms=0;ms<2;ms++)
                #pragma unroll
                for (int nt=0;nt<4;nt++)
                    #pragma unroll
                    for (int i=0;i<4;i++) acc[ms][nt][i]=0.f;
            #pragma unroll
            for (int kc = 0; kc < 2; kc++){
                int k0 = head*32 + kc*16;
                uint32_t ab = (uint32_t)((m0*136 + k0)*2);
                uint32_t ah0[4], ah1[4], al0[4], al1[4];
                ldsm4(ah0, sAh + ab + aoff);
                ldsm4(ah1, sAh + ab + 16u*136u*2u + aoff);
                ldsm4(al0, sAl + ab + aoff);
                ldsm4(al1, sAl + ab + 16u*136u*2u + aoff);
                #pragma unroll
                for (int nt = 0; nt < 4; nt++){
                    int nr = nb + nt*8;
                    uint32_t bb = (uint32_t)((nr*40 + kc*16)*2) + boffg;
                    uint32_t bh[2], bl[2];
                    ldsm2(bh, sWgh + bb);
                    ldsm2(bl, sWgl + bb);
                    mma3(acc[0][nt], ah0, al0, bh, bl);
                    mma3(acc[1][nt], ah1, al1, bh, bl);
                }
            }
            #pragma unroll
            for (int ms=0;ms<2;ms++){
                int tA = t0 + m0 + ms*16 + gr;
                int tB = tA + 8;
                int bA = tA>>6, sA = tA&63;
                int bB = tB>>6, sB = tB&63;
                float* dA = &g_gx[((size_t)(sA*Bm + bA))*512];
                float* dB = &g_gx[((size_t)(sB*Bm + bB))*512];
                #pragma unroll
                for (int nt=0;nt<4;nt++){
                    int col = nb + nt*8 + gc;
                    *reinterpret_cast<float2*>(dA + col) = make_float2(acc[ms][nt][0], acc[ms][nt][1]);
                    *reinterpret_cast<float2*>(dB + col) = make_float2(acc[ms][nt][2], acc[ms][nt][3]);
                }
            }
        }
    }
}

// ================= fused FF-down(blk1) + final LN + projection =================
#define DNP_SMEM (69632*2)
__global__ void __launch_bounds__(1024,1) k_downproj(const float* __restrict__ pw_ln,
                                                     const float* __restrict__ pjw,
                                                     const float* __restrict__ pjb,
                                                     float* __restrict__ out){
    extern __shared__ bf16 smp[];
    bf16 *Ah = smp, *Al = smp + 17408, *Wdh = smp + 34816, *Wdl = smp + 52224;
    int tid = threadIdx.x, w = tid>>5, lane = tid&31;
    for (int i = tid; i < 2048; i += 1024){
        int r = i>>4, c8 = (i&15)*8;
        *reinterpret_cast<uint4*>(Wdh + r*136 + c8) = *reinterpret_cast<const uint4*>(g_wdh + 16384 + r*128 + c8);
        *reinterpret_cast<uint4*>(Wdl + r*136 + c8) = *reinterpret_cast<const uint4*>(g_wdl + 16384 + r*128 + c8);
    }
    float4 pw = reinterpret_cast<const float4*>(pw_ln)[lane];
    #pragma unroll 1
    for (int mt = 0; mt < 2; mt++){
        int t0 = (blockIdx.x*2 + mt)*128;
        __syncthreads();
        down_tile(Ah, Al, Wdh, Wdl, t0, tid, w, lane);
        __syncthreads();
        #pragma unroll 1
        for (int i = 0; i < 4; i++){
            int t = t0 + w*4 + i;
            float4 v = reinterpret_cast<const float4*>(g_h + (size_t)t*128)[lane];
            float s = v.x+v.y+v.z+v.w;
            float q = v.x*v.x+v.y*v.y+v.z*v.z+v.w*v.w;
            #pragma unroll
            for (int o=16;o>0;o>>=1){ s += __shfl_xor_sync(0xffffffffu,s,o); q += __shfl_xor_sync(0xffffffffu,q,o); }
            float mu = s*(1.f/128.f);
            float inv = rsqrtf(q*(1.f/128.f) - mu*mu + EPSm);
            float4 xv;
            xv.x=(v.x-mu)*inv*pw.x; xv.y=(v.y-mu)*inv*pw.y;
            xv.z=(v.z-mu)*inv*pw.z; xv.w=(v.w-mu)*inv*pw.w;
            float res = 0.f;
            #pragma unroll
            for (int vc = 0; vc < 9; vc++){
                float4 p = reinterpret_cast<const float4*>(pjw + vc*Dm)[lane];
                float sv = xv.x*p.x + xv.y*p.y + xv.z*p.z + xv.w*p.w;
                #pragma unroll
                for (int o=16;o>0;o>>=1) sv += __shfl_xor_sync(0xffffffffu,sv,o);
                if (lane == vc) res = sv;
            }
            if (lane < 9) out[t*9 + lane] = res + pjb[lane];
        }
    }
}

// ---------------- sLSTM gate math (branchless) ----------------
__device__ __forceinline__ float slstm_step(float i_r, float f_r, float z_r, float o_r,
                                            float& c, float& nn, float& m){
    float lsf = fminf(f_r, 0.f) - __logf(1.f + __expf(-fabsf(f_r)));
    float lfm = m + lsf;
    float mnew = fmaxf(i_r, lfm);
    float ig = __expf(i_r - mnew);
    float fg = __expf(lfm - mnew);
    float e2z = __expf(2.f*z_r);
    float tz = 1.f - __fdividef(2.f, e2z + 1.f);
    c  = fg*c  + ig*tz;
    nn = fg*nn + ig;
    m  = mnew;
    float so = __fdividef(1.f, 1.f + __expf(-o_r));
    return so * __fdividef(c, nn);
}

// ================= sequential scan (proven R12 config: 2 batches/CTA, grid 256) =================
__global__ void __launch_bounds__(128,2) k_scan(const float* __restrict__ Rw,
                                                const float* __restrict__ bw,
                                                const float* __restrict__ gnw){
    __shared__ __align__(16) float hs[1024];
    int tid = threadIdx.x;
    int n = tid >> 5, k = tid & 31;
    int b0 = blockIdx.x*2, b1 = b0 + 1;

    ull r01[32], r23[32];
    const float* rp = Rw + n*4096 + k;
    #pragma unroll
    for (int h = 0; h < 32; h++){
        r01[h] = pk2(rp[h*128],      rp[h*128 + 32]);
        r23[h] = pk2(rp[h*128 + 64], rp[h*128 + 96]);
    }
    float bias0 = bw[(n*4+0)*32+k], bias1 = bw[(n*4+1)*32+k];
    float bias2 = bw[(n*4+2)*32+k], bias3 = bw[(n*4+3)*32+k];
    float gw = gnw[n*32+k];

    int o = n*32 + k;
    *reinterpret_cast<ull*>(&hs[o*2])       = 0ull;
    *reinterpret_cast<ull*>(&hs[256 + o*2]) = 0ull;
    float ca=0.f, na=0.f, ma=0.f, cb=0.f, nb=0.f, mb=0.f;
    __syncwarp();

    const float4* pga = reinterpret_cast<const float4*>(&g_gx[(size_t)b0*512 + o*4]);
    const float4* pgb = reinterpret_cast<const float4*>(&g_gx[(size_t)b1*512 + o*4]);
    float* hpA = &g_h[(size_t)(b0*64)*Dm + o];
    float* hpB = &g_h[(size_t)(b1*64)*Dm + o];
    float4 ga = pga[0], gb = pgb[0];
    int cur = 0;

    for (int s = 0; s < Sm; s++){
        float hresA = hpA[s*Dm];
        float hresB = hpB[s*Dm];
        float4 gan = ga, gbn = gb;
        if (s < Sm-1){ gan = pga[(s+1)*65536]; gbn = pgb[(s+1)*65536]; }
        ull a0e=0,a0o=0,a1e=0,a1o=0, c0e=0,c0o=0,c1e=0,c1o=0;
        const ulonglong2* hpa = reinterpret_cast<const ulonglong2*>(&hs[cur*512 + n*64]);
        const ulonglong2* hpb = reinterpret_cast<const ulonglong2*>(&hs[cur*512 + 256 + n*64]);
        #pragma unroll
        for (int hh = 0; hh < 16; hh++){
            ulonglong2 ha = hpa[hh];
            ulonglong2 hb = hpb[hh];
            a0e = fma2_(ha.x, r01[2*hh],   a0e);
            a1e = fma2_(ha.x, r23[2*hh],   a1e);
            c0e = fma2_(hb.x, r01[2*hh],   c0e);
            c1e = fma2_(hb.x, r23[2*hh],   c1e);
            a0o = fma2_(ha.y, r01[2*hh+1], a0o);
            a1o = fma2_(ha.y, r23[2*hh+1], a1o);
            c0o = fma2_(hb.y, r01[2*hh+1], c0o);
            c1o = fma2_(hb.y, r23[2*hh+1], c1o);
        }
        ull aa01 = add2_(a0e, a0o);
        ull aa23 = add2_(a1e, a1o);
        ull ab01 = add2_(c0e, c0o);
        ull ab23 = add2_(c1e, c1o);
        float ria,rfa,rza,roa, rib,rfb,rzb,rob;
        upk2(aa01,ria,rfa); upk2(aa23,rza,roa);
        upk2(ab01,rib,rfb); upk2(ab23,rzb,rob);
        float hn_a = slstm_step(ria+ga.x+bias0, rfa+ga.y+bias1, rza+ga.z+bias2, roa+ga.w+bias3, ca,na,ma);
        float hn_b = slstm_step(rib+gb.x+bias0, rfb+gb.y+bias1, rzb+gb.z+bias2, rob+gb.w+bias3, cb,nb,mb);
        int nxt = cur ^ 1;
        *reinterpret_cast<ull*>(&hs[nxt*512 + o*2])       = pk2(hn_a, hn_a);
        *reinterpret_cast<ull*>(&hs[nxt*512 + 256 + o*2]) = pk2(hn_b, hn_b);
        __syncwarp();
        float sa = hn_a, qa = hn_a*hn_a, sb2 = hn_b, qb = hn_b*hn_b;
        #pragma unroll
        for (int off=16; off>0; off>>=1){
            sa  += __shfl_xor_sync(0xffffffffu,sa,off);
            qa  += __shfl_xor_sync(0xffffffffu,qa,off);
            sb2 += __shfl_xor_sync(0xffffffffu,sb2,off);
            qb  += __shfl_xor_sync(0xffffffffu,qb,off);
        }
        float mua = sa*(1.f/32.f);
        float inva = rsqrtf(qa*(1.f/32.f) - mua*mua + EPSm);
        float mub = sb2*(1.f/32.f);
        float invb = rsqrtf(qb*(1.f/32.f) - mub*mub + EPSm);
        hpA[s*Dm] = hresA + (hn_a - mua)*inva*gw;
        hpB[s*Dm] = hresB + (hn_b - mub)*invb*gw;
        ga = gan; gb = gbn;
        cur = nxt;
    }
}

// ---------------- launch ----------------
extern "C" void kernel_launch(void* const* d_in, const int* in_sizes, int n_in,
                              void* d_out, int out_size){
    const int*   x      = (const int*)  d_in[0];
    const float* emb    = (const float*)d_in[1];
    const float* ln1_w  = (const float*)d_in[2];
    const float* Wg     = (const float*)d_in[3];
    const float* R      = (const float*)d_in[4];
    const float* bias   = (const float*)d_in[5];
    const float* gn_w   = (const float*)d_in[6];
    const float* ln2_w  = (const float*)d_in[7];
    const float* ffu    = (const float*)d_in[8];
    const float* ffd    = (const float*)d_in[9];
    const float* post_w = (const float*)d_in[10];
    const float* pjw    = (const float*)d_in[11];
    const float* pjb    = (const float*)d_in[12];
    float* out = (float*)d_out;

    cudaFuncSetAttribute(k_gx0,     cudaFuncAttributeMaxDynamicSharedMemorySize, GXS_SMEM);
    cudaFuncSetAttribute(k_up,      cudaFuncAttributeMaxDynamicSharedMemorySize, UPS_SMEM);
    cudaFuncSetAttribute(k_downgx,  cudaFuncAttributeMaxDynamicSharedMemorySize, DGX_SMEM);
    cudaFuncSetAttribute(k_downproj,cudaFuncAttributeMaxDynamicSharedMemorySize, DNP_SMEM);

    k_prep    <<<512,256>>>(Wg, ffu, ffd);
    k_gx0     <<<128,1024,GXS_SMEM>>>(x, emb, ln1_w);
    k_scan    <<<256,128>>>(R, bias, gn_w);
    k_up      <<<128,1024,UPS_SMEM>>>(0, ln2_w);
    k_downgx  <<<128,1024,DGX_SMEM>>>(ln1_w + Dm);
    k_scan    <<<256,128>>>(R + 16384, bias + 512, gn_w + Dm);
    k_up      <<<128,1024,UPS_SMEM>>>(1, ln2_w + Dm);
    k_downproj<<<128,1024,DNP_SMEM>>>(post_w, pjw, pjb, out);
}